// round 16
// baseline (speedup 1.0000x reference)
#include <cuda_runtime.h>
#include <cuda_fp16.h>
#include <stdint.h>

#define N_NODES 100000
#define N_EDGES 6400000
#define C 32
#define BN_EPS 1e-5f

#define SCAN_TB 512
#define SCAN_NB 196   // 196 * 512 = 100352 >= N_NODES

// ---------------- device scratch (static, zero-initialized at load) -----------
// NOTE: g_deg is re-zeroed by k_scanC at the end of every execution, so each
// run (first correctness call and every graph replay) starts with g_deg == 0.
__device__ int    g_is64;                 // 1 if edge_index is int64, else int32
__device__ int    g_deg[N_NODES];
__device__ int    g_bsum[SCAN_NB];        // per-block degree sums (raw, from scanA)
__device__ int    g_off[N_NODES + 1];     // CSR row offsets (by dst)
__device__ int    g_cur[N_NODES];         // fill cursors
__device__ int    g_csr[N_EDGES];         // src indices grouped by dst
__device__ float  g_dinv[N_NODES];
__device__ uint4  g_hphv[N_NODES * 4];    // h' fp16: 16 half2 per node (64B row)
__device__ float  g_z[N_NODES * C];       // pre-BN activations (fp32)
__device__ float  g_bn1[64];              // [0:32) sum, [32:64) sumsq
__device__ float  g_bn2[64];
__device__ float  g_hp3[N_NODES];

// ---------------- dtype detection (1 warp) -------------------------------------
__global__ void k_detect(const unsigned long long* __restrict__ ei) {
    if (threadIdx.x == 0) {
        int is64 = 1;
        for (int i = 0; i < 64; i++)
            if (ei[i] >= (unsigned long long)N_NODES) { is64 = 0; break; }
        g_is64 = is64;
    }
}

// ---------------- degree histogram (scalar: max atomic parallelism) ------------
__global__ void k_deg(const void* __restrict__ eiraw) {
    const int is64 = g_is64;
    int t = blockIdx.x * blockDim.x + threadIdx.x;
    int stride = gridDim.x * blockDim.x;
    if (is64) {
        const long long* ei = (const long long*)eiraw;
        for (int i = t; i < N_EDGES; i += stride) {
            int d = (int)ei[N_EDGES + i];
            if ((unsigned)d >= N_NODES) d = 0;
            atomicAdd(&g_deg[d], 1);
        }
    } else {
        const int* ei = (const int*)eiraw;
        for (int i = t; i < N_EDGES; i += stride) {
            int d = ei[N_EDGES + i];
            if ((unsigned)d >= N_NODES) d = 0;
            atomicAdd(&g_deg[d], 1);
        }
    }
}

// ---------------- phase A: per-block degree sums + bn zeroing -------------------
__global__ void k_scanA() {
    __shared__ int s[SCAN_TB];
    int t = threadIdx.x;
    if (blockIdx.x == 0 && t < 64) { g_bn1[t] = 0.f; g_bn2[t] = 0.f; }
    int i = blockIdx.x * SCAN_TB + t;
    s[t] = (i < N_NODES) ? g_deg[i] : 0;
    __syncthreads();
    for (int o = SCAN_TB / 2; o > 0; o >>= 1) {
        if (t < o) s[t] += s[t + o];
        __syncthreads();
    }
    if (t == 0) g_bsum[blockIdx.x] = s[0];
}

// ---------------- pack 32 fp32 channels -> 16 half2 -> 4 uint4 stores ----------
__device__ __forceinline__ void store_hph(int i, const float* o, float di) {
    uint32_t w[16];
#pragma unroll
    for (int cp = 0; cp < 16; cp++) {
        __half2 h = __floats2half2_rn(o[cp * 2] * di, o[cp * 2 + 1] * di);
        w[cp] = *reinterpret_cast<uint32_t*>(&h);
    }
#pragma unroll
    for (int q = 0; q < 4; q++)
        g_hphv[i * 4 + q] = make_uint4(w[q * 4], w[q * 4 + 1], w[q * 4 + 2], w[q * 4 + 3]);
}

// ---------------- phase C: block-sum scan (fused scanB) + intra-block scan ------
// + off/cur/dinv + FUSED layer1 + g_deg reset for next replay
__global__ void k_scanC(const float* __restrict__ x, const float* __restrict__ W1) {
    __shared__ int s[SCAN_TB];
    __shared__ int sb2[256];
    int t = threadIdx.x;

    // fused scanB: every block scans the 196 raw block sums locally
    if (t < 256) sb2[t] = (t < SCAN_NB) ? g_bsum[t] : 0;
    __syncthreads();
    for (int o = 1; o < 256; o <<= 1) {
        int u = (t < 256 && t >= o) ? sb2[t - o] : 0;
        __syncthreads();
        if (t < 256) sb2[t] += u;
        __syncthreads();
    }
    int base = (blockIdx.x > 0) ? sb2[blockIdx.x - 1] : 0;
    if (blockIdx.x == 0 && t == 0) g_off[N_NODES] = sb2[SCAN_NB - 1];

    int i = blockIdx.x * SCAN_TB + t;
    int d = (i < N_NODES) ? g_deg[i] : 0;
    s[t] = d;
    __syncthreads();
    for (int o = 1; o < SCAN_TB; o <<= 1) {
        int u = (t >= o) ? s[t - o] : 0;
        __syncthreads();
        s[t] += u;
        __syncthreads();
    }
    if (i < N_NODES) {
        int off = base + s[t] - d;                  // exclusive
        g_off[i] = off;
        g_cur[i] = off;
        g_deg[i] = 0;                               // reset for next replay
        float di = rsqrtf((float)(d + 1));          // +1 self-loop
        g_dinv[i] = di;
        // ---- fused layer 1: h' = (x @ W1) * dinv (fp16 out) ----
        float xv[5];
#pragma unroll
        for (int k = 0; k < 5; k++) xv[k] = x[i * 5 + k];
        float o[32];
#pragma unroll
        for (int c = 0; c < 32; c++) {
            float a = 0.f;
#pragma unroll
            for (int k = 0; k < 5; k++) a += xv[k] * __ldg(&W1[k * 32 + c]);
            o[c] = a;
        }
        store_hph(i, o, di);
    }
}

// ---------------- counting-sort fill (scalar: max atomic parallelism) ----------
__global__ void k_fill(const void* __restrict__ eiraw) {
    const int is64 = g_is64;
    int t = blockIdx.x * blockDim.x + threadIdx.x;
    int stride = gridDim.x * blockDim.x;
    if (is64) {
        const long long* ei = (const long long*)eiraw;
        for (int i = t; i < N_EDGES; i += stride) {
            int s = (int)ei[i];
            int d = (int)ei[N_EDGES + i];
            if ((unsigned)s >= N_NODES) s = 0;
            if ((unsigned)d >= N_NODES) d = 0;
            g_csr[atomicAdd(&g_cur[d], 1)] = s;
        }
    } else {
        const int* ei = (const int*)eiraw;
        for (int i = t; i < N_EDGES; i += stride) {
            int s = ei[i];
            int d = ei[N_EDGES + i];
            if ((unsigned)s >= N_NODES) s = 0;
            if ((unsigned)d >= N_NODES) d = 0;
            g_csr[atomicAdd(&g_cur[d], 1)] = s;
        }
    }
}

// ---------------- fused aggregate + z + BN stats (half2, 16-edge unroll) -------
// warp per node. lane&15 = channel pair; warp halves process alternate edges.
// 16 edges per iter => 8 independent half2 LDGs in flight per half-warp.
__global__ void k_agg32(const float* __restrict__ b, int which) {
    __shared__ float sb[64];
    float* bn = which ? g_bn2 : g_bn1;
    const __half2* hp = reinterpret_cast<const __half2*>(g_hphv);
    const int lane = threadIdx.x & 31;
    const int wid = threadIdx.x >> 5;
    const int nwpb = blockDim.x >> 5;
    if (threadIdx.x < 64) sb[threadIdx.x] = 0.f;
    __syncthreads();

    int node = blockIdx.x * nwpb + wid;
    if (node < N_NODES) {
        const int c = lane & 15;
        const int hf = lane >> 4;                    // 0: even edges, 1: odd edges
        int start = g_off[node];
        int end = g_off[node + 1];
        float ax = 0.f, ay = 0.f;
        for (int p = start; p < end; p += 32) {
            int m = end - p; if (m > 32) m = 32;
            int sidx = (lane < m) ? __ldg(&g_csr[p + lane]) : 0;
            int j = 0;
            for (; j + 16 <= m; j += 16) {
                int e0 = __shfl_sync(0xffffffffu, sidx, j + hf);
                int e1 = __shfl_sync(0xffffffffu, sidx, j + 2 + hf);
                int e2 = __shfl_sync(0xffffffffu, sidx, j + 4 + hf);
                int e3 = __shfl_sync(0xffffffffu, sidx, j + 6 + hf);
                int e4 = __shfl_sync(0xffffffffu, sidx, j + 8 + hf);
                int e5 = __shfl_sync(0xffffffffu, sidx, j + 10 + hf);
                int e6 = __shfl_sync(0xffffffffu, sidx, j + 12 + hf);
                int e7 = __shfl_sync(0xffffffffu, sidx, j + 14 + hf);
                float2 v0 = __half22float2(__ldg(&hp[e0 * 16 + c]));
                float2 v1 = __half22float2(__ldg(&hp[e1 * 16 + c]));
                float2 v2 = __half22float2(__ldg(&hp[e2 * 16 + c]));
                float2 v3 = __half22float2(__ldg(&hp[e3 * 16 + c]));
                float2 v4 = __half22float2(__ldg(&hp[e4 * 16 + c]));
                float2 v5 = __half22float2(__ldg(&hp[e5 * 16 + c]));
                float2 v6 = __half22float2(__ldg(&hp[e6 * 16 + c]));
                float2 v7 = __half22float2(__ldg(&hp[e7 * 16 + c]));
                ax += ((v0.x + v1.x) + (v2.x + v3.x)) + ((v4.x + v5.x) + (v6.x + v7.x));
                ay += ((v0.y + v1.y) + (v2.y + v3.y)) + ((v4.y + v5.y) + (v6.y + v7.y));
            }
            for (; j + 8 <= m; j += 8) {
                int e0 = __shfl_sync(0xffffffffu, sidx, j + hf);
                int e1 = __shfl_sync(0xffffffffu, sidx, j + 2 + hf);
                int e2 = __shfl_sync(0xffffffffu, sidx, j + 4 + hf);
                int e3 = __shfl_sync(0xffffffffu, sidx, j + 6 + hf);
                float2 v0 = __half22float2(__ldg(&hp[e0 * 16 + c]));
                float2 v1 = __half22float2(__ldg(&hp[e1 * 16 + c]));
                float2 v2 = __half22float2(__ldg(&hp[e2 * 16 + c]));
                float2 v3 = __half22float2(__ldg(&hp[e3 * 16 + c]));
                ax += (v0.x + v1.x) + (v2.x + v3.x);
                ay += (v0.y + v1.y) + (v2.y + v3.y);
            }
            for (; j + 2 <= m; j += 2) {
                int e0 = __shfl_sync(0xffffffffu, sidx, j + hf);
                float2 v0 = __half22float2(__ldg(&hp[e0 * 16 + c]));
                ax += v0.x;
                ay += v0.y;
            }
            if (j < m) {
                int e0 = __shfl_sync(0xffffffffu, sidx, j);
                if (!hf) {
                    float2 v0 = __half22float2(__ldg(&hp[e0 * 16 + c]));
                    ax += v0.x;
                    ay += v0.y;
                }
            }
        }
        // merge the two warp halves (same channel pair, disjoint edge subsets)
        ax += __shfl_xor_sync(0xffffffffu, ax, 16);
        ay += __shfl_xor_sync(0xffffffffu, ay, 16);
        if (!hf) {
            float2 sl = __half22float2(hp[node * 16 + c]);   // self-loop
            ax += sl.x; ay += sl.y;
            float di = g_dinv[node];
            float v0 = di * ax + b[2 * c];
            float v1 = di * ay + b[2 * c + 1];
            reinterpret_cast<float2*>(g_z)[node * 16 + c] = make_float2(v0, v1);
            atomicAdd(&sb[2 * c], v0);
            atomicAdd(&sb[2 * c + 1], v1);
            atomicAdd(&sb[32 + 2 * c], v0 * v0);
            atomicAdd(&sb[32 + 2 * c + 1], v1 * v1);
        }
    }
    __syncthreads();
    if (threadIdx.x < 64) atomicAdd(&bn[threadIdx.x], sb[threadIdx.x]);
}

// ---------------- layer 2 (BN params computed in-block from sums) ---------------
__global__ void k_layer2(const float* __restrict__ W2,
                         const float* __restrict__ gamma, const float* __restrict__ beta,
                         int which) {
    __shared__ float sW[1024];
    __shared__ float sa[32], sc[32];
    const float* bn = which ? g_bn2 : g_bn1;
    for (int t = threadIdx.x; t < 1024; t += blockDim.x) sW[t] = W2[t];
    if (threadIdx.x < 32) {
        int ch = threadIdx.x;
        float inv_n = 1.0f / (float)N_NODES;
        float m = bn[ch] * inv_n;
        float var = bn[32 + ch] * inv_n - m * m;
        float a = gamma[ch] * rsqrtf(var + BN_EPS);
        sa[ch] = a;
        sc[ch] = beta[ch] - m * a;
    }
    __syncthreads();
    int i = blockIdx.x * blockDim.x + threadIdx.x;
    if (i >= N_NODES) return;
    float y[32];
#pragma unroll
    for (int c = 0; c < 32; c++)
        y[c] = fmaxf(g_z[i * 32 + c] * sa[c] + sc[c], 0.f);
    float o[32];
#pragma unroll
    for (int c2 = 0; c2 < 32; c2++) o[c2] = 0.f;
#pragma unroll
    for (int c = 0; c < 32; c++) {
        float yv = y[c];
#pragma unroll
        for (int c2 = 0; c2 < 32; c2++) o[c2] += yv * sW[c * 32 + c2];
    }
    store_hph(i, o, g_dinv[i]);
}

// ---------------- layer 3 (BN params computed in-block from sums) ---------------
__global__ void k_layer3(const float* __restrict__ W3,
                         const float* __restrict__ gamma, const float* __restrict__ beta,
                         int which) {
    __shared__ float sa[32], sc[32];
    const float* bn = which ? g_bn2 : g_bn1;
    if (threadIdx.x < 32) {
        int ch = threadIdx.x;
        float inv_n = 1.0f / (float)N_NODES;
        float m = bn[ch] * inv_n;
        float var = bn[32 + ch] * inv_n - m * m;
        float a = gamma[ch] * rsqrtf(var + BN_EPS);
        sa[ch] = a;
        sc[ch] = beta[ch] - m * a;
    }
    __syncthreads();
    int i = blockIdx.x * blockDim.x + threadIdx.x;
    if (i >= N_NODES) return;
    float acc = 0.f;
#pragma unroll
    for (int c = 0; c < 32; c++) {
        float v = g_z[i * 32 + c] * sa[c] + sc[c];
        v = fmaxf(v, 0.f);
        acc += v * __ldg(&W3[c]);
    }
    g_hp3[i] = acc * g_dinv[i];
}

// ---------------- final: out = dinv*(sum_in hp3 + hp3) + b3 --------------------
__global__ void k_agg1(const float* __restrict__ b3, float* __restrict__ out) {
    const int lane = threadIdx.x & 31;
    const int wid = threadIdx.x >> 5;
    const int nwpb = blockDim.x >> 5;
    int node = blockIdx.x * nwpb + wid;
    if (node >= N_NODES) return;
    int start = g_off[node];
    int end = g_off[node + 1];
    float a = 0.f;
    for (int p = start + lane; p < end; p += 32)
        a += __ldg(&g_hp3[__ldg(&g_csr[p])]);
#pragma unroll
    for (int o = 16; o; o >>= 1) a += __shfl_xor_sync(0xffffffffu, a, o);
    if (lane == 0)
        out[node] = g_dinv[node] * (a + g_hp3[node]) + b3[0];
}

// =============================================================================
extern "C" void kernel_launch(void* const* d_in, const int* in_sizes, int n_in,
                              void* d_out, int out_size) {
    const float* x      = (const float*)d_in[0];
    const void*  ei     = d_in[1];
    const float* W1     = (const float*)d_in[2];
    const float* b1     = (const float*)d_in[3];
    const float* gamma1 = (const float*)d_in[4];
    const float* beta1  = (const float*)d_in[5];
    const float* W2     = (const float*)d_in[6];
    const float* b2     = (const float*)d_in[7];
    const float* gamma2 = (const float*)d_in[8];
    const float* beta2  = (const float*)d_in[9];
    const float* W3     = (const float*)d_in[10];
    const float* b3     = (const float*)d_in[11];
    float* out = (float*)d_out;

    const int TB = 256;
    const int nodeBlocks = (N_NODES + TB - 1) / TB;          // 391
    const int edgeBlocks = (N_EDGES + TB - 1) / TB;          // 25000
    const int warpBlocks = (N_NODES * 32 + TB - 1) / TB;     // 12500 (warp/node)

    k_detect<<<1, 32>>>((const unsigned long long*)ei);
    k_deg<<<edgeBlocks, TB>>>(ei);
    k_scanA<<<SCAN_NB, SCAN_TB>>>();
    k_scanC<<<SCAN_NB, SCAN_TB>>>(x, W1);   // fused scanB + layer 1 + deg reset
    k_fill<<<edgeBlocks, TB>>>(ei);

    // ---- layer 1 aggregation
    k_agg32<<<warpBlocks, TB>>>(b1, 0);

    // ---- layer 2 (BN params inlined)
    k_layer2<<<nodeBlocks, TB>>>(W2, gamma1, beta1, 0);
    k_agg32<<<warpBlocks, TB>>>(b2, 1);

    // ---- layer 3 (BN params inlined)
    k_layer3<<<nodeBlocks, TB>>>(W3, gamma2, beta2, 1);
    k_agg1<<<warpBlocks, TB>>>(b3, out);
}

// round 17
// speedup vs baseline: 1.0809x; 1.0809x over previous
#include <cuda_runtime.h>
#include <cuda_fp16.h>
#include <stdint.h>

#define N_NODES 100000
#define N_EDGES 6400000
#define C 32
#define BN_EPS 1e-5f

#define SCAN_TB 512
#define SCAN_NB 196   // 196 * 512 = 100352 >= N_NODES

// ---------------- device scratch (static, zero-initialized at load) -----------
// NOTE: g_deg is re-zeroed by k_scanC at the end of every execution, so each
// run (first correctness call and every graph replay) starts with g_deg == 0.
__device__ int    g_deg[N_NODES];
__device__ int    g_bsum[SCAN_NB];        // per-block degree sums (raw, from scanA)
__device__ int    g_off[N_NODES + 1];     // CSR row offsets (by dst)
__device__ int    g_cur[N_NODES];         // fill cursors
__device__ int    g_csr[N_EDGES];         // src indices grouped by dst
__device__ float  g_dinv[N_NODES];
__device__ uint4  g_hphv[N_NODES * 4];    // h' fp16: 16 half2 per node (64B row)
__device__ uint4  g_zv[N_NODES * 4];      // pre-BN activations fp16 (16 half2/node)
__device__ float  g_bn1[64];              // [0:32) sum, [32:64) sumsq
__device__ float  g_bn2[64];
__device__ float  g_hp3[N_NODES];

// ---------------- per-block dtype detection ------------------------------------
// int32 pairs read as u64 are >= 2^32 unless dst==0 (prob ~1e-5 each);
// genuine int64 indices are all < N_NODES. 16 words => unambiguous.
__device__ __forceinline__ int detect_is64(const void* eiraw) {
    const unsigned long long* e64 = (const unsigned long long*)eiraw;
    int is64 = 1;
#pragma unroll
    for (int i = 0; i < 16; i++)
        if (__ldg(&e64[i]) >= (unsigned long long)N_NODES) { is64 = 0; break; }
    return is64;
}

// ---------------- degree histogram (scalar: max atomic parallelism) ------------
__global__ void k_deg(const void* __restrict__ eiraw) {
    __shared__ int s_is64;
    if (threadIdx.x == 0) s_is64 = detect_is64(eiraw);
    __syncthreads();
    const int is64 = s_is64;
    int t = blockIdx.x * blockDim.x + threadIdx.x;
    int stride = gridDim.x * blockDim.x;
    if (is64) {
        const long long* ei = (const long long*)eiraw;
        for (int i = t; i < N_EDGES; i += stride) {
            int d = (int)ei[N_EDGES + i];
            if ((unsigned)d >= N_NODES) d = 0;
            atomicAdd(&g_deg[d], 1);
        }
    } else {
        const int* ei = (const int*)eiraw;
        for (int i = t; i < N_EDGES; i += stride) {
            int d = ei[N_EDGES + i];
            if ((unsigned)d >= N_NODES) d = 0;
            atomicAdd(&g_deg[d], 1);
        }
    }
}

// ---------------- phase A: per-block degree sums + bn zeroing -------------------
__global__ void k_scanA() {
    __shared__ int s[SCAN_TB];
    int t = threadIdx.x;
    if (blockIdx.x == 0 && t < 64) { g_bn1[t] = 0.f; g_bn2[t] = 0.f; }
    int i = blockIdx.x * SCAN_TB + t;
    s[t] = (i < N_NODES) ? g_deg[i] : 0;
    __syncthreads();
    for (int o = SCAN_TB / 2; o > 0; o >>= 1) {
        if (t < o) s[t] += s[t + o];
        __syncthreads();
    }
    if (t == 0) g_bsum[blockIdx.x] = s[0];
}

// ---------------- pack 32 fp32 channels -> 16 half2 -> 4 uint4 stores ----------
__device__ __forceinline__ void store_hph(int i, const float* o, float di) {
    uint32_t w[16];
#pragma unroll
    for (int cp = 0; cp < 16; cp++) {
        __half2 h = __floats2half2_rn(o[cp * 2] * di, o[cp * 2 + 1] * di);
        w[cp] = *reinterpret_cast<uint32_t*>(&h);
    }
#pragma unroll
    for (int q = 0; q < 4; q++)
        g_hphv[i * 4 + q] = make_uint4(w[q * 4], w[q * 4 + 1], w[q * 4 + 2], w[q * 4 + 3]);
}

// ---------------- phase C: block-sum scan (fused scanB) + intra-block scan ------
// + off/cur/dinv + FUSED layer1 + g_deg reset for next replay
__global__ void k_scanC(const float* __restrict__ x, const float* __restrict__ W1) {
    __shared__ int s[SCAN_TB];
    __shared__ int sb2[256];
    int t = threadIdx.x;

    // fused scanB: every block scans the 196 raw block sums locally
    if (t < 256) sb2[t] = (t < SCAN_NB) ? g_bsum[t] : 0;
    __syncthreads();
    for (int o = 1; o < 256; o <<= 1) {
        int u = (t < 256 && t >= o) ? sb2[t - o] : 0;
        __syncthreads();
        if (t < 256) sb2[t] += u;
        __syncthreads();
    }
    int base = (blockIdx.x > 0) ? sb2[blockIdx.x - 1] : 0;
    if (blockIdx.x == 0 && t == 0) g_off[N_NODES] = sb2[SCAN_NB - 1];

    int i = blockIdx.x * SCAN_TB + t;
    int d = (i < N_NODES) ? g_deg[i] : 0;
    s[t] = d;
    __syncthreads();
    for (int o = 1; o < SCAN_TB; o <<= 1) {
        int u = (t >= o) ? s[t - o] : 0;
        __syncthreads();
        s[t] += u;
        __syncthreads();
    }
    if (i < N_NODES) {
        int off = base + s[t] - d;                  // exclusive
        g_off[i] = off;
        g_cur[i] = off;
        g_deg[i] = 0;                               // reset for next replay
        float di = rsqrtf((float)(d + 1));          // +1 self-loop
        g_dinv[i] = di;
        // ---- fused layer 1: h' = (x @ W1) * dinv (fp16 out) ----
        float xv[5];
#pragma unroll
        for (int k = 0; k < 5; k++) xv[k] = x[i * 5 + k];
        float o[32];
#pragma unroll
        for (int c = 0; c < 32; c++) {
            float a = 0.f;
#pragma unroll
            for (int k = 0; k < 5; k++) a += xv[k] * __ldg(&W1[k * 32 + c]);
            o[c] = a;
        }
        store_hph(i, o, di);
    }
}

// ---------------- counting-sort fill (scalar: max atomic parallelism) ----------
__global__ void k_fill(const void* __restrict__ eiraw) {
    __shared__ int s_is64;
    if (threadIdx.x == 0) s_is64 = detect_is64(eiraw);
    __syncthreads();
    const int is64 = s_is64;
    int t = blockIdx.x * blockDim.x + threadIdx.x;
    int stride = gridDim.x * blockDim.x;
    if (is64) {
        const long long* ei = (const long long*)eiraw;
        for (int i = t; i < N_EDGES; i += stride) {
            int s = (int)ei[i];
            int d = (int)ei[N_EDGES + i];
            if ((unsigned)s >= N_NODES) s = 0;
            if ((unsigned)d >= N_NODES) d = 0;
            g_csr[atomicAdd(&g_cur[d], 1)] = s;
        }
    } else {
        const int* ei = (const int*)eiraw;
        for (int i = t; i < N_EDGES; i += stride) {
            int s = ei[i];
            int d = ei[N_EDGES + i];
            if ((unsigned)s >= N_NODES) s = 0;
            if ((unsigned)d >= N_NODES) d = 0;
            g_csr[atomicAdd(&g_cur[d], 1)] = s;
        }
    }
}

// ---------------- fused aggregate + z(fp16) + BN stats (half2, 16-edge unroll) -
// warp per node. lane&15 = channel pair; warp halves process alternate edges.
// 16 edges per iter => 8 independent half2 LDGs in flight per half-warp.
__global__ void k_agg32(const float* __restrict__ b, int which) {
    __shared__ float sb[64];
    float* bn = which ? g_bn2 : g_bn1;
    const __half2* hp = reinterpret_cast<const __half2*>(g_hphv);
    __half2* zp = reinterpret_cast<__half2*>(g_zv);
    const int lane = threadIdx.x & 31;
    const int wid = threadIdx.x >> 5;
    const int nwpb = blockDim.x >> 5;
    if (threadIdx.x < 64) sb[threadIdx.x] = 0.f;
    __syncthreads();

    int node = blockIdx.x * nwpb + wid;
    if (node < N_NODES) {
        const int c = lane & 15;
        const int hf = lane >> 4;                    // 0: even edges, 1: odd edges
        int start = g_off[node];
        int end = g_off[node + 1];
        float ax = 0.f, ay = 0.f;
        for (int p = start; p < end; p += 32) {
            int m = end - p; if (m > 32) m = 32;
            int sidx = (lane < m) ? __ldg(&g_csr[p + lane]) : 0;
            int j = 0;
            for (; j + 16 <= m; j += 16) {
                int e0 = __shfl_sync(0xffffffffu, sidx, j + hf);
                int e1 = __shfl_sync(0xffffffffu, sidx, j + 2 + hf);
                int e2 = __shfl_sync(0xffffffffu, sidx, j + 4 + hf);
                int e3 = __shfl_sync(0xffffffffu, sidx, j + 6 + hf);
                int e4 = __shfl_sync(0xffffffffu, sidx, j + 8 + hf);
                int e5 = __shfl_sync(0xffffffffu, sidx, j + 10 + hf);
                int e6 = __shfl_sync(0xffffffffu, sidx, j + 12 + hf);
                int e7 = __shfl_sync(0xffffffffu, sidx, j + 14 + hf);
                float2 v0 = __half22float2(__ldg(&hp[e0 * 16 + c]));
                float2 v1 = __half22float2(__ldg(&hp[e1 * 16 + c]));
                float2 v2 = __half22float2(__ldg(&hp[e2 * 16 + c]));
                float2 v3 = __half22float2(__ldg(&hp[e3 * 16 + c]));
                float2 v4 = __half22float2(__ldg(&hp[e4 * 16 + c]));
                float2 v5 = __half22float2(__ldg(&hp[e5 * 16 + c]));
                float2 v6 = __half22float2(__ldg(&hp[e6 * 16 + c]));
                float2 v7 = __half22float2(__ldg(&hp[e7 * 16 + c]));
                ax += ((v0.x + v1.x) + (v2.x + v3.x)) + ((v4.x + v5.x) + (v6.x + v7.x));
                ay += ((v0.y + v1.y) + (v2.y + v3.y)) + ((v4.y + v5.y) + (v6.y + v7.y));
            }
            for (; j + 8 <= m; j += 8) {
                int e0 = __shfl_sync(0xffffffffu, sidx, j + hf);
                int e1 = __shfl_sync(0xffffffffu, sidx, j + 2 + hf);
                int e2 = __shfl_sync(0xffffffffu, sidx, j + 4 + hf);
                int e3 = __shfl_sync(0xffffffffu, sidx, j + 6 + hf);
                float2 v0 = __half22float2(__ldg(&hp[e0 * 16 + c]));
                float2 v1 = __half22float2(__ldg(&hp[e1 * 16 + c]));
                float2 v2 = __half22float2(__ldg(&hp[e2 * 16 + c]));
                float2 v3 = __half22float2(__ldg(&hp[e3 * 16 + c]));
                ax += (v0.x + v1.x) + (v2.x + v3.x);
                ay += (v0.y + v1.y) + (v2.y + v3.y);
            }
            for (; j + 2 <= m; j += 2) {
                int e0 = __shfl_sync(0xffffffffu, sidx, j + hf);
                float2 v0 = __half22float2(__ldg(&hp[e0 * 16 + c]));
                ax += v0.x;
                ay += v0.y;
            }
            if (j < m) {
                int e0 = __shfl_sync(0xffffffffu, sidx, j);
                if (!hf) {
                    float2 v0 = __half22float2(__ldg(&hp[e0 * 16 + c]));
                    ax += v0.x;
                    ay += v0.y;
                }
            }
        }
        // merge the two warp halves (same channel pair, disjoint edge subsets)
        ax += __shfl_xor_sync(0xffffffffu, ax, 16);
        ay += __shfl_xor_sync(0xffffffffu, ay, 16);
        if (!hf) {
            float2 sl = __half22float2(hp[node * 16 + c]);   // self-loop
            ax += sl.x; ay += sl.y;
            float di = g_dinv[node];
            float v0 = di * ax + b[2 * c];
            float v1 = di * ay + b[2 * c + 1];
            zp[node * 16 + c] = __floats2half2_rn(v0, v1);
            atomicAdd(&sb[2 * c], v0);
            atomicAdd(&sb[2 * c + 1], v1);
            atomicAdd(&sb[32 + 2 * c], v0 * v0);
            atomicAdd(&sb[32 + 2 * c + 1], v1 * v1);
        }
    }
    __syncthreads();
    if (threadIdx.x < 64) atomicAdd(&bn[threadIdx.x], sb[threadIdx.x]);
}

// ---------------- load 32 z channels (fp16 row) into fp32 regs ------------------
__device__ __forceinline__ void load_z(int i, float* z) {
#pragma unroll
    for (int q = 0; q < 4; q++) {
        uint4 w = g_zv[i * 4 + q];
        const uint32_t ww[4] = { w.x, w.y, w.z, w.w };
#pragma unroll
        for (int k = 0; k < 4; k++) {
            __half2 h = *reinterpret_cast<const __half2*>(&ww[k]);
            float2 f = __half22float2(h);
            z[q * 8 + k * 2] = f.x;
            z[q * 8 + k * 2 + 1] = f.y;
        }
    }
}

// ---------------- layer 2 (BN params computed in-block from sums) ---------------
__global__ void k_layer2(const float* __restrict__ W2,
                         const float* __restrict__ gamma, const float* __restrict__ beta,
                         int which) {
    __shared__ float sW[1024];
    __shared__ float sa[32], sc[32];
    const float* bn = which ? g_bn2 : g_bn1;
    for (int t = threadIdx.x; t < 1024; t += blockDim.x) sW[t] = W2[t];
    if (threadIdx.x < 32) {
        int ch = threadIdx.x;
        float inv_n = 1.0f / (float)N_NODES;
        float m = bn[ch] * inv_n;
        float var = bn[32 + ch] * inv_n - m * m;
        float a = gamma[ch] * rsqrtf(var + BN_EPS);
        sa[ch] = a;
        sc[ch] = beta[ch] - m * a;
    }
    __syncthreads();
    int i = blockIdx.x * blockDim.x + threadIdx.x;
    if (i >= N_NODES) return;
    float zr[32];
    load_z(i, zr);
    float y[32];
#pragma unroll
    for (int c = 0; c < 32; c++)
        y[c] = fmaxf(zr[c] * sa[c] + sc[c], 0.f);
    float o[32];
#pragma unroll
    for (int c2 = 0; c2 < 32; c2++) o[c2] = 0.f;
#pragma unroll
    for (int c = 0; c < 32; c++) {
        float yv = y[c];
#pragma unroll
        for (int c2 = 0; c2 < 32; c2++) o[c2] += yv * sW[c * 32 + c2];
    }
    store_hph(i, o, g_dinv[i]);
}

// ---------------- layer 3 (BN params computed in-block from sums) ---------------
__global__ void k_layer3(const float* __restrict__ W3,
                         const float* __restrict__ gamma, const float* __restrict__ beta,
                         int which) {
    __shared__ float sa[32], sc[32];
    const float* bn = which ? g_bn2 : g_bn1;
    if (threadIdx.x < 32) {
        int ch = threadIdx.x;
        float inv_n = 1.0f / (float)N_NODES;
        float m = bn[ch] * inv_n;
        float var = bn[32 + ch] * inv_n - m * m;
        float a = gamma[ch] * rsqrtf(var + BN_EPS);
        sa[ch] = a;
        sc[ch] = beta[ch] - m * a;
    }
    __syncthreads();
    int i = blockIdx.x * blockDim.x + threadIdx.x;
    if (i >= N_NODES) return;
    float zr[32];
    load_z(i, zr);
    float acc = 0.f;
#pragma unroll
    for (int c = 0; c < 32; c++) {
        float v = zr[c] * sa[c] + sc[c];
        v = fmaxf(v, 0.f);
        acc += v * __ldg(&W3[c]);
    }
    g_hp3[i] = acc * g_dinv[i];
}

// ---------------- final: out = dinv*(sum_in hp3 + hp3) + b3 --------------------
__global__ void k_agg1(const float* __restrict__ b3, float* __restrict__ out) {
    const int lane = threadIdx.x & 31;
    const int wid = threadIdx.x >> 5;
    const int nwpb = blockDim.x >> 5;
    int node = blockIdx.x * nwpb + wid;
    if (node >= N_NODES) return;
    int start = g_off[node];
    int end = g_off[node + 1];
    float a = 0.f;
    for (int p = start + lane; p < end; p += 32)
        a += __ldg(&g_hp3[__ldg(&g_csr[p])]);
#pragma unroll
    for (int o = 16; o; o >>= 1) a += __shfl_xor_sync(0xffffffffu, a, o);
    if (lane == 0)
        out[node] = g_dinv[node] * (a + g_hp3[node]) + b3[0];
}

// =============================================================================
extern "C" void kernel_launch(void* const* d_in, const int* in_sizes, int n_in,
                              void* d_out, int out_size) {
    const float* x      = (const float*)d_in[0];
    const void*  ei     = d_in[1];
    const float* W1     = (const float*)d_in[2];
    const float* b1     = (const float*)d_in[3];
    const float* gamma1 = (const float*)d_in[4];
    const float* beta1  = (const float*)d_in[5];
    const float* W2     = (const float*)d_in[6];
    const float* b2     = (const float*)d_in[7];
    const float* gamma2 = (const float*)d_in[8];
    const float* beta2  = (const float*)d_in[9];
    const float* W3     = (const float*)d_in[10];
    const float* b3     = (const float*)d_in[11];
    float* out = (float*)d_out;

    const int TB = 256;
    const int nodeBlocks = (N_NODES + TB - 1) / TB;          // 391
    const int edgeBlocks = (N_EDGES + TB - 1) / TB;          // 25000
    const int warpBlocks = (N_NODES * 32 + TB - 1) / TB;     // 12500 (warp/node)

    k_deg<<<edgeBlocks, TB>>>(ei);
    k_scanA<<<SCAN_NB, SCAN_TB>>>();
    k_scanC<<<SCAN_NB, SCAN_TB>>>(x, W1);   // fused scanB + layer 1 + deg reset
    k_fill<<<edgeBlocks, TB>>>(ei);

    // ---- layer 1 aggregation
    k_agg32<<<warpBlocks, TB>>>(b1, 0);

    // ---- layer 2 (BN params inlined)
    k_layer2<<<nodeBlocks, TB>>>(W2, gamma1, beta1, 0);
    k_agg32<<<warpBlocks, TB>>>(b2, 1);

    // ---- layer 3 (BN params inlined)
    k_layer3<<<nodeBlocks, TB>>>(W3, gamma2, beta2, 1);
    k_agg1<<<warpBlocks, TB>>>(b3, out);
}